// round 9
// baseline (speedup 1.0000x reference)
#include <cuda_runtime.h>
#include <cuda_fp16.h>
#include <cstdint>
#include <math.h>

#define Bn 128
#define Tn 256
#define Hn 128
#define Cn 10

typedef unsigned int u32;
typedef unsigned short u16;

__device__ __forceinline__ float tanh_fast(float v) {
    float y;
    asm("tanh.approx.f32 %0, %1;" : "=f"(y) : "f"(v));
    return y;
}
__device__ __forceinline__ u32 smem_u32(const void* p) {
    u32 a;
    asm("{ .reg .u64 t; cvta.to.shared.u64 t, %1; cvt.u32.u64 %0, t; }" : "=r"(a) : "l"(p));
    return a;
}
__device__ __forceinline__ u32 mapa_u32(u32 addr, u32 rank) {
    u32 r;
    asm("mapa.shared::cluster.u32 %0, %1, %2;" : "=r"(r) : "r"(addr), "r"(rank));
    return r;
}
__device__ __forceinline__ void st_cluster_u16(u32 addr, u16 v) {
    asm volatile("st.shared::cluster.u16 [%0], %1;" :: "r"(addr), "h"(v) : "memory");
}
__device__ __forceinline__ void mbar_arrive_remote(u32 addr) {
    asm volatile("mbarrier.arrive.release.cluster.shared::cluster.b64 _, [%0];"
                 :: "r"(addr) : "memory");
}
__device__ __forceinline__ void mbar_wait(u32 addr, u32 parity) {
    asm volatile(
        "{\n\t.reg .pred P;\n\t"
        "WL_%=:\n\t"
        "mbarrier.try_wait.parity.acquire.cluster.shared::cta.b64 P, [%0], %1, 0x989680;\n\t"
        "@P bra.uni WD_%=;\n\t"
        "bra.uni WL_%=;\n\t"
        "WD_%=:\n\t}"
        :: "r"(addr), "r"(parity) : "memory");
}

// smem layout (bytes):
//   0      H16[257][128] fp16 (history; row t+1 = h_t; row 0 = h0 = 0)   65792
//   65792  sP[256][12] f32                                              12288
//   78080  sA[256] f32
//   79104  sS[256] f32
//   80128  x_sh[256] f32
//   81152  mbar[2] (8 B each)
#define OFF_SP   65792
#define OFF_SA   78080
#define OFF_SS   79104
#define OFF_X    80128
#define OFF_MBAR 81152
#define SMEM_SZ  81280

// ---------------------------------------------------------------------------
// Cluster of 2 CTAs = one batch row. CTA r owns hidden units [64r, 64r+64).
// 512 threads: warp w (0..15) owns j = 64r + 4w + jj; lane l = half*16+gt*4+jj,
// k-slice [64*half, 64*half+64), 32 half2 weight regs.
// Per step: HFMA2 matvec -> xor16 k-combine -> 1 MUFU.TANH all-gates ->
// xor8/xor4 dance -> h on gt1 lanes; half0-gt1 stores own H16 row t+1,
// half1-gt1 stores peer's row via DSMEM + release-arrive on peer mbar[t&1].
// All threads: __syncthreads, then acquire-wait own mbar[t&1].
// ---------------------------------------------------------------------------
__global__ __launch_bounds__(512, 2) __cluster_dims__(2, 1, 1)
void lstm_cluster(
    const float* __restrict__ x,
    const float* __restrict__ W_ih,
    const float* __restrict__ W_hh,
    const float* __restrict__ b_ih,
    const float* __restrict__ b_hh,
    const float* __restrict__ w_t,
    const float* __restrict__ fc_W,
    const float* __restrict__ fc_b,
    float* __restrict__ out)
{
    extern __shared__ __align__(16) char smraw[];
    __half* H16  = (__half*)smraw;
    float*  sP   = (float*)(smraw + OFF_SP);
    float*  sA   = (float*)(smraw + OFF_SA);
    float*  sS   = (float*)(smraw + OFF_SS);
    float*  x_sh = (float*)(smraw + OFF_X);

    const u32 sbase = smem_u32(smraw);
    const u32 mb0 = sbase + OFF_MBAR;
    const u32 mb1 = sbase + OFF_MBAR + 8;

    const int b    = blockIdx.x >> 1;   // cluster id = batch row
    const int r    = blockIdx.x & 1;    // rank in cluster
    const int tid  = threadIdx.x;
    const int w    = tid >> 5;          // 0..15
    const int l    = tid & 31;
    const int jj   = l & 3;
    const int gt   = (l >> 2) & 3;
    const int k0   = (l >> 4) * 64;
    const int jown = 64 * r + (w << 2) + jj;        // owned hidden unit
    const int g    = gt * Hn + jown;                // gate row in W_hh

    // ---- W_hh k-slice -> 32 half2 registers ----
    half2 w2[32];
    {
        const float* wrow = W_hh + g * Hn + k0;
#pragma unroll
        for (int i = 0; i < 32; i++)
            w2[i] = __floats2half2_rn(wrow[2 * i], wrow[2 * i + 1]);
    }
    const float wih_r  = W_ih[g];
    const float bias_r = b_ih[g] + b_hh[g];

    if (tid == 0) {
        asm volatile("mbarrier.init.shared.b64 [%0], 64;" :: "r"(mb0) : "memory");
        asm volatile("mbarrier.init.shared.b64 [%0], 64;" :: "r"(mb1) : "memory");
        asm volatile("fence.mbarrier_init.release.cluster;" ::: "memory");
    }
    if (tid < Hn) H16[tid] = __float2half(0.f);     // row 0 = h0 = 0
    if (tid < Tn) x_sh[tid] = x[b * Tn + tid];
    __syncthreads();
    asm volatile("barrier.cluster.arrive.aligned;" ::: "memory");
    asm volatile("barrier.cluster.wait.aligned;"   ::: "memory");

    const u32 peerH   = mapa_u32(sbase, r ^ 1);
    const u32 peerMb0 = mapa_u32(mb0, r ^ 1);
    const u32 peerMb1 = mapa_u32(mb1, r ^ 1);

    // ================= Phase 1: recurrence =================
    float c = 0.f;
#pragma unroll 2
    for (int t = 0; t < Tn; t++) {
        const uint4* hp = (const uint4*)(H16 + t * Hn + k0);
        half2 a0 = __float2half2_rn(0.f), a1 = a0, a2 = a0, a3 = a0;
#pragma unroll
        for (int q = 0; q < 4; q++) {
            uint4 hv = hp[q];
            a0 = __hfma2(w2[4 * q + 0], *(const half2*)&hv.x, a0);
            a1 = __hfma2(w2[4 * q + 1], *(const half2*)&hv.y, a1);
            a2 = __hfma2(w2[4 * q + 2], *(const half2*)&hv.z, a2);
            a3 = __hfma2(w2[4 * q + 3], *(const half2*)&hv.w, a3);
        }
#pragma unroll
        for (int q = 4; q < 8; q++) {
            uint4 hv = hp[q];
            a0 = __hfma2(w2[4 * q + 0], *(const half2*)&hv.x, a0);
            a1 = __hfma2(w2[4 * q + 1], *(const half2*)&hv.y, a1);
            a2 = __hfma2(w2[4 * q + 2], *(const half2*)&hv.z, a2);
            a3 = __hfma2(w2[4 * q + 3], *(const half2*)&hv.w, a3);
        }
        float2 f01 = __half22float2(__hadd2(a0, a1));
        float2 f23 = __half22float2(__hadd2(a2, a3));
        float sum = (f01.x + f01.y) + (f23.x + f23.y);
        if (l < 16) sum += fmaf(x_sh[t], wih_r, bias_r);
        sum += __shfl_xor_sync(0xffffffffu, sum, 16);      // k-combine (dup halves)

        const bool isg = (gt == 2);
        float tv  = tanh_fast(isg ? sum : 0.5f * sum);
        float act = isg ? tv : fmaf(0.5f, tv, 0.5f);       // gt0:si gt1:sf gt2:tg gt3:so

        float x8 = __shfl_xor_sync(0xffffffffu, act, 8);   // gt0<-tg gt1<-so gt2<-si gt3<-sf
        float v  = ((gt & 1) == 0) ? act * x8 : act;       // even: itg; odd: own sigma
        float x4 = __shfl_xor_sync(0xffffffffu, v, 4);     // gt1,gt3 <- itg

        float sfv = (gt == 1) ? act : x8;
        float sov = (gt == 1) ? x8  : act;
        c = fmaf(sfv, c, x4);                              // real on gt1, gt3 lanes
        float h = sov * tanh_fast(c);

        if (gt == 1) {
            u16 hu = __half_as_ushort(__float2half_rn(h));
            if (l < 16) {
                H16[(t + 1) * Hn + jown] = __ushort_as_half(hu);
            } else {
                st_cluster_u16(peerH + ((t + 1) * Hn + jown) * 2, hu);
                mbar_arrive_remote((t & 1) ? peerMb1 : peerMb0);
            }
        }
        __syncthreads();
        mbar_wait((t & 1) ? mb1 : mb0, (t >> 1) & 1);
    }

    // ================= Phase 2: a, s, p (full, redundant per CTA) ==========
    for (int i = 0; i < 16; i++) {
        const int t = (w << 4) + i;
        const __half* hrow = H16 + (t + 1) * Hn;           // h_t
        float h0 = __half2float(hrow[l]);
        float h1 = __half2float(hrow[l + 32]);
        float h2 = __half2float(hrow[l + 64]);
        float h3 = __half2float(hrow[l + 96]);
        float t0 = tanh_fast(h0), t1 = tanh_fast(h1), t2 = tanh_fast(h2), t3 = tanh_fast(h3);

        float v[12];
        v[0] = t0 * w_t[l]       + t1 * w_t[l + 32]  + t2 * w_t[l + 64]  + t3 * w_t[l + 96];
        v[1] = t0 * w_t[128 + l] + t1 * w_t[160 + l] + t2 * w_t[192 + l] + t3 * w_t[224 + l];
#pragma unroll
        for (int cc = 0; cc < Cn; cc++) {
            const float* fw = fc_W + cc * Hn;
            v[2 + cc] = h0 * fw[l] + h1 * fw[l + 32] + h2 * fw[l + 64] + h3 * fw[l + 96];
        }
#pragma unroll
        for (int off = 16; off > 0; off >>= 1)
#pragma unroll
            for (int k = 0; k < 12; k++)
                v[k] += __shfl_xor_sync(0xffffffffu, v[k], off);
        if (l == 0) {
            sA[t] = v[0];
            sS[t] = v[1];
            float* pr = sP + t * 12;
#pragma unroll
            for (int cc = 0; cc < Cn; cc++) pr[cc] = v[2 + cc];
            pr[10] = 0.f; pr[11] = 0.f;
        }
    }
    __syncthreads();

    // ================= Phase 3: attention + output (t ≡ r mod 2) ==========
    {
        const int tl   = tid >> 2;                  // 0..127
        const int t    = (tl << 1) | r;             // interleaved across cluster
        const int part = tid & 3;
        const float at = sA[t];
        float acc[10];
#pragma unroll
        for (int i = 0; i < 10; i++) acc[i] = 0.f;

        const int jmaxW = ((tid >> 5) << 4) + 15;   // warp-uniform bound (>= max t-1)
        for (int jm1 = part; jm1 < jmaxW; jm1 += 4) {
            float wgt = __fdividef(1.f, 1.f + __expf(-(at + sS[jm1])));
            wgt = (jm1 < t) ? wgt : 0.f;
            const float4* q = (const float4*)(sP + jm1 * 12);
            float4 q0 = q[0], q1 = q[1], q2 = q[2];
            acc[0] = fmaf(wgt, q0.x, acc[0]); acc[1] = fmaf(wgt, q0.y, acc[1]);
            acc[2] = fmaf(wgt, q0.z, acc[2]); acc[3] = fmaf(wgt, q0.w, acc[3]);
            acc[4] = fmaf(wgt, q1.x, acc[4]); acc[5] = fmaf(wgt, q1.y, acc[5]);
            acc[6] = fmaf(wgt, q1.z, acc[6]); acc[7] = fmaf(wgt, q1.w, acc[7]);
            acc[8] = fmaf(wgt, q2.x, acc[8]); acc[9] = fmaf(wgt, q2.y, acc[9]);
        }
#pragma unroll
        for (int off = 1; off <= 2; off <<= 1)
#pragma unroll
            for (int i = 0; i < 10; i++)
                acc[i] += __shfl_xor_sync(0xffffffffu, acc[i], off);

        if (part == 0) {
            float* o = out + (b * Tn + t) * Cn;
            const float* pr = sP + t * 12;
#pragma unroll
            for (int i = 0; i < 10; i++)
                o[i] = acc[i] + pr[i] + fc_b[i];
        }
    }

    // final cluster barrier: no CTA exits while peer could still be mid-exchange
    asm volatile("barrier.cluster.arrive.aligned;" ::: "memory");
    asm volatile("barrier.cluster.wait.aligned;"   ::: "memory");
}

// ============================================================================
extern "C" void kernel_launch(void* const* d_in, const int* in_sizes, int n_in,
                              void* d_out, int out_size)
{
    const float* x    = (const float*)d_in[0];
    const float* W_ih = (const float*)d_in[1];
    const float* W_hh = (const float*)d_in[2];
    const float* b_ih = (const float*)d_in[3];
    const float* b_hh = (const float*)d_in[4];
    const float* w_t  = (const float*)d_in[5];
    const float* fc_W = (const float*)d_in[6];
    const float* fc_b = (const float*)d_in[7];
    float* out = (float*)d_out;

    // Idempotent; also runs on the pre-capture correctness call.
    cudaFuncSetAttribute(lstm_cluster, cudaFuncAttributeMaxDynamicSharedMemorySize, SMEM_SZ);

    lstm_cluster<<<2 * Bn, 512, SMEM_SZ>>>(x, W_ih, W_hh, b_ih, b_hh,
                                           w_t, fc_W, fc_b, out);
}

// round 10
// speedup vs baseline: 1.3964x; 1.3964x over previous
#include <cuda_runtime.h>
#include <cuda_fp16.h>
#include <cstdint>
#include <math.h>

#define Bn 128
#define Tn 256
#define Hn 128
#define Cn 10

__device__ __forceinline__ float tanh_fast(float v) {
    float y;
    asm("tanh.approx.f32 %0, %1;" : "=f"(y) : "f"(v));
    return y;
}
#define NB_SYNC(id, cnt)   asm volatile("bar.sync %0, %1;"   :: "r"(id), "r"(cnt) : "memory")
#define NB_ARRIVE(id, cnt) asm volatile("bar.arrive %0, %1;" :: "r"(id), "r"(cnt) : "memory")

// smem layout (bytes):
//   0      Hf[256][128] f32 history                     131072
//   131072 sP[256][12] f32                               12288
//   143360 sA[256] f32
//   144384 sS[256] f32
//   145408 x_sh[256] f32
//   146432 red[2][2][544] f32 partial sums (t-parity, hf, 4*136 rows)  8704
//   155136 h16[2][128] fp16 ping-pong                      512
#define OFF_SP  131072
#define OFF_SA  143360
#define OFF_SS  144384
#define OFF_X   145408
#define OFF_RED 146432
#define OFF_H16 155136
#define SMEM_SZ 155648

// ---------------------------------------------------------------------------
// 1024 threads = 2 groups x 512. Group X owns hidden units [64X, 64X+64):
// 256 gate rows x 2 warp-level k-halves. Warp w: X=w>>4, wl=w&15, hf=wl>>3,
// wq=wl&7; lane: jn=l&7, gt=l>>3 -> unit j=64X+8wq+jn, gate row g=gt*128+j,
// k-slice [64hf, 64hf+64). 32 half2 weight regs/thread.
//
// Named barriers (count incl. producer arrivals):
//   id1: chunk A (units 0..63) ready.  syncs: all hf0 warps (512). arrives: w0,w1 (64).
//   id2: chunk B ready.                syncs: all hf1 warps (512). arrives: w18,w19 (64).
//   id3/id4: group-internal bar (512) between partial STS and update.
// Update warps (2 per group, distinct SMSPs) do the LSTM cell update for
// their group's 64 units, store h (fp16 ping + f32 history), then arrive.
// The two groups run 1 step apart at most; each group's serial update tail
// overlaps the other group's matvec.
// ---------------------------------------------------------------------------
__global__ __launch_bounds__(1024, 1) void lstm_fused(
    const float* __restrict__ x,
    const float* __restrict__ W_ih,
    const float* __restrict__ W_hh,
    const float* __restrict__ b_ih,
    const float* __restrict__ b_hh,
    const float* __restrict__ w_t,
    const float* __restrict__ fc_W,
    const float* __restrict__ fc_b,
    float* __restrict__ out)
{
    extern __shared__ __align__(16) char smraw[];
    float*  Hf   = (float*)smraw;
    float*  sP   = (float*)(smraw + OFF_SP);
    float*  sA   = (float*)(smraw + OFF_SA);
    float*  sS   = (float*)(smraw + OFF_SS);
    float*  x_sh = (float*)(smraw + OFF_X);
    float*  red  = (float*)(smraw + OFF_RED);   // [2][2][544]
    __half* h16  = (__half*)(smraw + OFF_H16);  // [2][128]

    const int tid = threadIdx.x;
    const int b   = blockIdx.x;
    const int w   = tid >> 5;
    const int l   = tid & 31;
    const int X   = w >> 4;            // group
    const int wl  = w & 15;
    const int hf  = wl >> 3;           // warp-uniform k-half
    const int wq  = wl & 7;
    const int jn  = l & 7;
    const int gt  = l >> 3;            // gate 0:i 1:f 2:g 3:o
    const int j   = 64 * X + 8 * wq + jn;   // source unit row
    const int g   = gt * Hn + j;            // gate row in W_hh
    const int k0  = 64 * hf;

    // update warps: group0 -> w0,w1 (SMSP 0,1); group1 -> w18,w19 (SMSP 2,3)
    const bool isupd = (X == 0) ? (wl < 2) : (wl >= 2 && wl < 4);
    const int  ju    = 64 * X + ((X == 0) ? wl : (wl - 2)) * 32 + l;  // owned unit

    // ---- W_hh k-slice -> 32 half2 registers ----
    half2 w2[32];
    {
        const float* wrow = W_hh + g * Hn + k0;
#pragma unroll
        for (int i = 0; i < 32; i++)
            w2[i] = __floats2half2_rn(wrow[2 * i], wrow[2 * i + 1]);
    }
    const float wih_r  = W_ih[g];
    const float bias_r = b_ih[g] + b_hh[g];

    if (tid < Tn) x_sh[tid] = x[b * Tn + tid];
    if (tid < 2 * Hn) h16[tid] = __float2half(0.f);   // both ping slots = 0
    __syncthreads();

    // pre-arm chunk barriers: h(-1) is "ready"
    if (isupd) NB_ARRIVE(1 + X, 576);

    const int myChunkBar = 1 + hf;     // barrier for the chunk this warp consumes
    const int myGroupBar = 3 + X;

    // ================= Phase 1: recurrence =================
    float c = 0.f;
    for (int t = 0; t < Tn; t++) {
        NB_SYNC(myChunkBar, 576);                       // wait chunk hf of h(t-1)

        const uint4* hp = (const uint4*)(h16 + ((t + 1) & 1) * Hn + k0);
        half2 a0 = __float2half2_rn(0.f), a1 = a0, a2 = a0, a3 = a0;
#pragma unroll
        for (int q = 0; q < 4; q++) {
            uint4 hv = hp[q];
            a0 = __hfma2(w2[4 * q + 0], *(const half2*)&hv.x, a0);
            a1 = __hfma2(w2[4 * q + 1], *(const half2*)&hv.y, a1);
            a2 = __hfma2(w2[4 * q + 2], *(const half2*)&hv.z, a2);
            a3 = __hfma2(w2[4 * q + 3], *(const half2*)&hv.w, a3);
        }
#pragma unroll
        for (int q = 4; q < 8; q++) {
            uint4 hv = hp[q];
            a0 = __hfma2(w2[4 * q + 0], *(const half2*)&hv.x, a0);
            a1 = __hfma2(w2[4 * q + 1], *(const half2*)&hv.y, a1);
            a2 = __hfma2(w2[4 * q + 2], *(const half2*)&hv.z, a2);
            a3 = __hfma2(w2[4 * q + 3], *(const half2*)&hv.w, a3);
        }
        float2 f01 = __half22float2(__hadd2(a0, a1));
        float2 f23 = __half22float2(__hadd2(a2, a3));
        float sum = (f01.x + f01.y) + (f23.x + f23.y);
        if (hf == 0) sum += fmaf(x_sh[t], wih_r, bias_r);   // add once per row

        // conflict-free partial store: bank = gt*8 + jn (136 stride)
        red[(t & 1) * 1088 + hf * 544 + gt * 136 + j] = sum;

        NB_SYNC(myGroupBar, 512);                       // group partials visible

        if (isupd) {
            const float* rp = red + (t & 1) * 1088;
            float gi = rp[0 * 136 + ju] + rp[544 + 0 * 136 + ju];
            float gf = rp[1 * 136 + ju] + rp[544 + 1 * 136 + ju];
            float gg = rp[2 * 136 + ju] + rp[544 + 2 * 136 + ju];
            float go = rp[3 * 136 + ju] + rp[544 + 3 * 136 + ju];
            float si = fmaf(0.5f, tanh_fast(0.5f * gi), 0.5f);
            float sf = fmaf(0.5f, tanh_fast(0.5f * gf), 0.5f);
            float tg = tanh_fast(gg);
            float so = fmaf(0.5f, tanh_fast(0.5f * go), 0.5f);
            c = fmaf(sf, c, si * tg);
            float h = so * tanh_fast(c);
            h16[(t & 1) * Hn + ju] = __float2half_rn(h);
            Hf[t * Hn + ju] = h;
            if (t < Tn - 1) NB_ARRIVE(1 + X, 576);      // publish chunk X of h(t)
        }
    }
    __syncthreads();

    // ================= Phase 2: a, s, p per t (warp w: rows 8w..8w+7) =======
    for (int i = 0; i < 8; i++) {
        const int t = (w << 3) + i;
        const float* hrow = Hf + t * Hn;
        float h0 = hrow[l], h1 = hrow[l + 32], h2 = hrow[l + 64], h3 = hrow[l + 96];
        float t0 = tanh_fast(h0), t1 = tanh_fast(h1), t2 = tanh_fast(h2), t3 = tanh_fast(h3);

        float v[12];
        v[0] = t0 * w_t[l]       + t1 * w_t[l + 32]  + t2 * w_t[l + 64]  + t3 * w_t[l + 96];
        v[1] = t0 * w_t[128 + l] + t1 * w_t[160 + l] + t2 * w_t[192 + l] + t3 * w_t[224 + l];
#pragma unroll
        for (int cc = 0; cc < Cn; cc++) {
            const float* fw = fc_W + cc * Hn;
            v[2 + cc] = h0 * fw[l] + h1 * fw[l + 32] + h2 * fw[l + 64] + h3 * fw[l + 96];
        }
#pragma unroll
        for (int off = 16; off > 0; off >>= 1)
#pragma unroll
            for (int k = 0; k < 12; k++)
                v[k] += __shfl_xor_sync(0xffffffffu, v[k], off);
        if (l == 0) {
            sA[t] = v[0];
            sS[t] = v[1];
            float* pr = sP + t * 12;
#pragma unroll
            for (int cc = 0; cc < Cn; cc++) pr[cc] = v[2 + cc];
            pr[10] = 0.f; pr[11] = 0.f;
        }
    }
    __syncthreads();

    // ================= Phase 3: attention + output =================
    {
        const int t    = tid >> 2;
        const int part = tid & 3;
        const float at = sA[t];
        float acc[10];
#pragma unroll
        for (int i = 0; i < 10; i++) acc[i] = 0.f;

        const int jmaxW = (w << 3) + 7;            // warp-uniform bound
        for (int jm1 = part; jm1 < jmaxW; jm1 += 4) {
            float wgt = __fdividef(1.f, 1.f + __expf(-(at + sS[jm1])));
            wgt = (jm1 < t) ? wgt : 0.f;
            const float4* q = (const float4*)(sP + jm1 * 12);
            float4 q0 = q[0], q1 = q[1], q2 = q[2];
            acc[0] = fmaf(wgt, q0.x, acc[0]); acc[1] = fmaf(wgt, q0.y, acc[1]);
            acc[2] = fmaf(wgt, q0.z, acc[2]); acc[3] = fmaf(wgt, q0.w, acc[3]);
            acc[4] = fmaf(wgt, q1.x, acc[4]); acc[5] = fmaf(wgt, q1.y, acc[5]);
            acc[6] = fmaf(wgt, q1.z, acc[6]); acc[7] = fmaf(wgt, q1.w, acc[7]);
            acc[8] = fmaf(wgt, q2.x, acc[8]); acc[9] = fmaf(wgt, q2.y, acc[9]);
        }
#pragma unroll
        for (int off = 1; off <= 2; off <<= 1)
#pragma unroll
            for (int i = 0; i < 10; i++)
                acc[i] += __shfl_xor_sync(0xffffffffu, acc[i], off);

        if (part == 0) {
            float* o = out + (b * Tn + t) * Cn;
            const float* pr = sP + t * 12;
#pragma unroll
            for (int i = 0; i < 10; i++)
                o[i] = acc[i] + pr[i] + fc_b[i];
        }
    }
}

// ============================================================================
extern "C" void kernel_launch(void* const* d_in, const int* in_sizes, int n_in,
                              void* d_out, int out_size)
{
    const float* x    = (const float*)d_in[0];
    const float* W_ih = (const float*)d_in[1];
    const float* W_hh = (const float*)d_in[2];
    const float* b_ih = (const float*)d_in[3];
    const float* b_hh = (const float*)d_in[4];
    const float* w_t  = (const float*)d_in[5];
    const float* fc_W = (const float*)d_in[6];
    const float* fc_b = (const float*)d_in[7];
    float* out = (float*)d_out;

    // Idempotent; also runs on the pre-capture correctness call.
    cudaFuncSetAttribute(lstm_fused, cudaFuncAttributeMaxDynamicSharedMemorySize, SMEM_SZ);

    lstm_fused<<<Bn, 1024, SMEM_SZ>>>(x, W_ih, W_hh, b_ih, b_hh,
                                      w_t, fc_W, fc_b, out);
}

// round 12
// speedup vs baseline: 1.4879x; 1.0655x over previous
#include <cuda_runtime.h>
#include <cuda_fp16.h>
#include <cstdint>
#include <math.h>

#define Bn 128
#define Tn 256
#define Hn 128
#define Cn 10

__device__ __forceinline__ float tanh_fast(float v) {
    float y;
    asm("tanh.approx.f32 %0, %1;" : "=f"(y) : "f"(v));
    return y;
}

// smem layout (bytes):
//   0      H16[257][128] fp16 history (row t+1 = h_t; row 0 = h0 = 0)  65792
//   65792  sP[256][12] f32                                            12288
//   78080  sA[256] f32
//   79104  sS[256] f32
//   80128  x_sh[256] f32
#define OFF_SP  65792
#define OFF_SA  78080
#define OFF_SS  79104
#define OFF_X   80128
#define SMEM_SZ 81152

// ---------------------------------------------------------------------------
// Fused kernel, 1024 threads/CTA, CTA b = batch row b.
// Phase 1, R=2 layout: lane l = kq*8 + p*4 + ju  (kq=l>>3, p=(l>>2)&1, ju=l&3)
//   unit j = 4w + ju;  thread computes TWO gate rows over k-quarter
//   [32kq, 32kq+32):  p=0 -> rows (i, f) of j ; p=1 -> rows (g, o) of j.
//   Each loaded h value feeds both rows -> h-operand smem traffic halves
//   vs one-row-per-thread (the measured LDS-writeback floor of prior rounds).
// Reduction: fp32, xor8 + xor16 over k-quarters (per row); then xor4 swaps
// activations between (i,f)- and (g,o)-lanes; every lane finishes c,h locally.
// h stored once (lanes p==1,kq==0) as fp16 into the history row t+1.
// One __syncthreads per step.
// ---------------------------------------------------------------------------
__global__ __launch_bounds__(1024, 1) void lstm_fused(
    const float* __restrict__ x,
    const float* __restrict__ W_ih,
    const float* __restrict__ W_hh,
    const float* __restrict__ b_ih,
    const float* __restrict__ b_hh,
    const float* __restrict__ w_t,
    const float* __restrict__ fc_W,
    const float* __restrict__ fc_b,
    float* __restrict__ out)
{
    extern __shared__ __align__(16) char smraw[];
    __half* H16  = (__half*)smraw;
    float*  sP   = (float*)(smraw + OFF_SP);
    float*  sA   = (float*)(smraw + OFF_SA);
    float*  sS   = (float*)(smraw + OFF_SS);
    float*  x_sh = (float*)(smraw + OFF_X);

    const int b   = blockIdx.x;
    const int tid = threadIdx.x;
    const int w   = tid >> 5;
    const int l   = tid & 31;
    const int ju  = l & 3;
    const int p   = (l >> 2) & 1;
    const int kq  = l >> 3;
    const int j   = (w << 2) + ju;            // hidden unit
    const int rowA = (p ? 2 : 0) * Hn + j;    // i-gate or g-gate row
    const int rowB = (p ? 3 : 1) * Hn + j;    // f-gate or o-gate row
    const int k0   = kq << 5;                 // k-quarter start

    // ---- weights: 16 half2 per row ----
    half2 wA[16], wB[16];
    {
        const float* ra = W_hh + rowA * Hn + k0;
        const float* rb = W_hh + rowB * Hn + k0;
#pragma unroll
        for (int i = 0; i < 16; i++) {
            wA[i] = __floats2half2_rn(ra[2 * i], ra[2 * i + 1]);
            wB[i] = __floats2half2_rn(rb[2 * i], rb[2 * i + 1]);
        }
    }
    const float wihA = W_ih[rowA], biasA = b_ih[rowA] + b_hh[rowA];
    const float wihB = W_ih[rowB], biasB = b_ih[rowB] + b_hh[rowB];
    // rowA activation constants: p=0 -> sigmoid(i); p=1 -> tanh(g)
    const float scA = p ? 1.0f : 0.5f;
    const float amA = p ? 1.0f : 0.5f;
    const float abA = p ? 0.0f : 0.5f;
    const bool  st_h = (p == 1) && (kq == 0);

    if (tid < Tn) x_sh[tid] = x[b * Tn + tid];
    if (tid < Hn) H16[tid] = __float2half(0.f);   // row 0 = h0 = 0
    __syncthreads();

    // ================= Phase 1: recurrence =================
    float c = 0.f;
#pragma unroll 2
    for (int t = 0; t < Tn; t++) {
        const uint4* hp = (const uint4*)(H16 + t * Hn + k0);
        half2 aA0 = __float2half2_rn(0.f), aA1 = aA0, aB0 = aA0, aB1 = aA0;
#pragma unroll
        for (int q = 0; q < 4; q++) {
            uint4 hv = hp[q];
            half2 h0 = *(const half2*)&hv.x, h1 = *(const half2*)&hv.y;
            half2 h2v = *(const half2*)&hv.z, h3 = *(const half2*)&hv.w;
            aA0 = __hfma2(wA[4 * q + 0], h0, aA0);
            aB0 = __hfma2(wB[4 * q + 0], h0, aB0);
            aA1 = __hfma2(wA[4 * q + 1], h1, aA1);
            aB1 = __hfma2(wB[4 * q + 1], h1, aB1);
            aA0 = __hfma2(wA[4 * q + 2], h2v, aA0);
            aB0 = __hfma2(wB[4 * q + 2], h2v, aB0);
            aA1 = __hfma2(wA[4 * q + 3], h3, aA1);
            aB1 = __hfma2(wB[4 * q + 3], h3, aB1);
        }
        float2 fA = __half22float2(__hadd2(aA0, aA1));
        float2 fB = __half22float2(__hadd2(aB0, aB1));
        float sAx = fA.x + fA.y;
        float sBx = fB.x + fB.y;
        // fp32 reduction over the 4 k-quarters (lane bits 3,4)
        sAx += __shfl_xor_sync(0xffffffffu, sAx, 8);
        sBx += __shfl_xor_sync(0xffffffffu, sBx, 8);
        sAx += __shfl_xor_sync(0xffffffffu, sAx, 16);
        sBx += __shfl_xor_sync(0xffffffffu, sBx, 16);

        const float xt = x_sh[t];
        float gA = sAx + fmaf(xt, wihA, biasA);
        float gB = sBx + fmaf(xt, wihB, biasB);

        // activations: rowA = sigmoid(i) | tanh(g); rowB = sigmoid(f|o)
        float actA = fmaf(amA, tanh_fast(scA * gA), abA);
        float actB = fmaf(0.5f, tanh_fast(0.5f * gB), 0.5f);

        // pair exchange (lane bit 2): get the other pair's activations
        float oA = __shfl_xor_sync(0xffffffffu, actA, 4);   // p0<-tg, p1<-si
        float oB = __shfl_xor_sync(0xffffffffu, actB, 4);   // p0<-so, p1<-sf
        float si = p ? oA : actA;
        float tg = p ? actA : oA;
        float sf = p ? oB : actB;
        // (so only needed where h is stored; compute everywhere, cheap)
        float so = p ? actB : oB;

        c = fmaf(sf, c, si * tg);
        float h = so * tanh_fast(c);

        if (st_h) H16[(t + 1) * Hn + j] = __float2half_rn(h);
        __syncthreads();
    }

    // ================= Phase 2: a, s, p per t (warp w: rows 8w..8w+7) =======
    for (int i = 0; i < 8; i++) {
        const int t = (w << 3) + i;
        const __half* hrow = H16 + (t + 1) * Hn;
        float h0 = __half2float(hrow[l]);
        float h1 = __half2float(hrow[l + 32]);
        float h2 = __half2float(hrow[l + 64]);
        float h3 = __half2float(hrow[l + 96]);
        float t0 = tanh_fast(h0), t1 = tanh_fast(h1), t2 = tanh_fast(h2), t3 = tanh_fast(h3);

        float v[12];
        v[0] = t0 * w_t[l]       + t1 * w_t[l + 32]  + t2 * w_t[l + 64]  + t3 * w_t[l + 96];
        v[1] = t0 * w_t[128 + l] + t1 * w_t[160 + l] + t2 * w_t[192 + l] + t3 * w_t[224 + l];
#pragma unroll
        for (int cc = 0; cc < Cn; cc++) {
            const float* fw = fc_W + cc * Hn;
            v[2 + cc] = h0 * fw[l] + h1 * fw[l + 32] + h2 * fw[l + 64] + h3 * fw[l + 96];
        }
#pragma unroll
        for (int off = 16; off > 0; off >>= 1)
#pragma unroll
            for (int k = 0; k < 12; k++)
                v[k] += __shfl_xor_sync(0xffffffffu, v[k], off);
        if (l == 0) {
            sA[t] = v[0];
            sS[t] = v[1];
            float* pr = sP + t * 12;
#pragma unroll
            for (int cc = 0; cc < Cn; cc++) pr[cc] = v[2 + cc];
            pr[10] = 0.f; pr[11] = 0.f;
        }
    }
    __syncthreads();

    // ================= Phase 3: attention + output =================
    {
        const int t    = tid >> 2;
        const int part = tid & 3;
        const float at = sA[t];
        float acc[10];
#pragma unroll
        for (int i = 0; i < 10; i++) acc[i] = 0.f;

        const int jmaxW = (w << 3) + 7;            // warp-uniform bound
        for (int jm1 = part; jm1 < jmaxW; jm1 += 4) {
            float wgt = __fdividef(1.f, 1.f + __expf(-(at + sS[jm1])));
            wgt = (jm1 < t) ? wgt : 0.f;
            const float4* q = (const float4*)(sP + jm1 * 12);
            float4 q0 = q[0], q1 = q[1], q2 = q[2];
            acc[0] = fmaf(wgt, q0.x, acc[0]); acc[1] = fmaf(wgt, q0.y, acc[1]);
            acc[2] = fmaf(wgt, q0.z, acc[2]); acc[3] = fmaf(wgt, q0.w, acc[3]);
            acc[4] = fmaf(wgt, q1.x, acc[4]); acc[5] = fmaf(wgt, q1.y, acc[5]);
            acc[6] = fmaf(wgt, q1.z, acc[6]); acc[7] = fmaf(wgt, q1.w, acc[7]);
            acc[8] = fmaf(wgt, q2.x, acc[8]); acc[9] = fmaf(wgt, q2.y, acc[9]);
        }
#pragma unroll
        for (int off = 1; off <= 2; off <<= 1)
#pragma unroll
            for (int i = 0; i < 10; i++)
                acc[i] += __shfl_xor_sync(0xffffffffu, acc[i], off);

        if (part == 0) {
            float* o = out + (b * Tn + t) * Cn;
            const float* pr = sP + t * 12;
#pragma unroll
            for (int i = 0; i < 10; i++)
                o[i] = acc[i] + pr[i] + fc_b[i];
        }
    }
}

// ============================================================================
extern "C" void kernel_launch(void* const* d_in, const int* in_sizes, int n_in,
                              void* d_out, int out_size)
{
    const float* x    = (const float*)d_in[0];
    const float* W_ih = (const float*)d_in[1];
    const float* W_hh = (const float*)d_in[2];
    const float* b_ih = (const float*)d_in[3];
    const float* b_hh = (const float*)d_in[4];
    const float* w_t  = (const float*)d_in[5];
    const float* fc_W = (const float*)d_in[6];
    const float* fc_b = (const float*)d_in[7];
    float* out = (float*)d_out;

    // Idempotent; also runs on the pre-capture correctness call.
    cudaFuncSetAttribute(lstm_fused, cudaFuncAttributeMaxDynamicSharedMemorySize, SMEM_SZ);

    lstm_fused<<<Bn, 1024, SMEM_SZ>>>(x, W_ih, W_hh, b_ih, b_hh,
                                      w_t, fc_W, fc_b, out);
}

// round 13
// speedup vs baseline: 1.5493x; 1.0413x over previous
#include <cuda_runtime.h>
#include <cuda_fp16.h>
#include <cstdint>
#include <math.h>

#define Bn 128
#define Tn 256
#define Hn 128
#define Cn 10

__device__ __forceinline__ float tanh_fast(float v) {
    float y;
    asm("tanh.approx.f32 %0, %1;" : "=f"(y) : "f"(v));
    return y;
}

// smem layout (bytes):
//   0      H16[257][128] fp16 history (row t+1 = h_t; row 0 = h0 = 0)  65792
//   65792  sP[256][12] f32                                            12288
//   78080  sA[256] f32
//   79104  sS[256] f32
//   80128  x_sh[256] f32
#define OFF_SP  65792
#define OFF_SA  78080
#define OFF_SS  79104
#define OFF_X   80128
#define SMEM_SZ 81152

// ---------------------------------------------------------------------------
// Fused kernel, 1024 threads/CTA, CTA b = batch row b.
// Phase 1, R=2 layout: lane l = kq*8 + p*4 + ju (kq=l>>3, p=(l>>2)&1, ju=l&3)
//   unit j = 4w + ju; thread computes TWO gate rows over k-quarter
//   [32kq,32kq+32): p=0 -> rows (i,f); p=1 -> rows (g,o).
// Role-swapped reduction (2 shfl): xor8 sends the OTHER row's partial, so
// even-kq lanes accumulate rowA (i|g), odd-kq lanes rowB (f|o); xor16
// completes the sum. Each lane then owns ONE gate -> one MUFU.TANH with
// per-thread constants. xor4 pairs si<->tg (even) and sf<->so (odd);
// even lanes form itg = si*tg; xor8 ships itg to odd lanes, which carry c
// and compute h. h stored from (p=1,kq=1) lanes. One __syncthreads/step.
// ---------------------------------------------------------------------------
__global__ __launch_bounds__(1024, 1) void lstm_fused(
    const float* __restrict__ x,
    const float* __restrict__ W_ih,
    const float* __restrict__ W_hh,
    const float* __restrict__ b_ih,
    const float* __restrict__ b_hh,
    const float* __restrict__ w_t,
    const float* __restrict__ fc_W,
    const float* __restrict__ fc_b,
    float* __restrict__ out)
{
    extern __shared__ __align__(16) char smraw[];
    __half* H16  = (__half*)smraw;
    float*  sP   = (float*)(smraw + OFF_SP);
    float*  sA   = (float*)(smraw + OFF_SA);
    float*  sS   = (float*)(smraw + OFF_SS);
    float*  x_sh = (float*)(smraw + OFF_X);

    const int b   = blockIdx.x;
    const int tid = threadIdx.x;
    const int w   = tid >> 5;
    const int l   = tid & 31;
    const int ju  = l & 3;
    const int p   = (l >> 2) & 1;
    const int kq  = l >> 3;
    const int j   = (w << 2) + ju;            // hidden unit
    const int rowA = (p ? 2 : 0) * Hn + j;    // i-gate or g-gate row
    const int rowB = (p ? 3 : 1) * Hn + j;    // f-gate or o-gate row
    const int k0   = kq << 5;                 // k-quarter start

    const bool evenkq = (kq & 1) == 0;
    const int  rowAct = evenkq ? rowA : rowB; // the gate this lane activates
    const bool isg    = (p == 1) && evenkq;   // g-gate -> plain tanh
    const float sc = isg ? 1.0f : 0.5f;
    const float am = isg ? 1.0f : 0.5f;
    const float ab = isg ? 0.0f : 0.5f;
    const bool st_h = (p == 1) && (kq == 1);

    // ---- weights: 16 half2 per row ----
    half2 wA[16], wB[16];
    {
        const float* ra = W_hh + rowA * Hn + k0;
        const float* rb = W_hh + rowB * Hn + k0;
#pragma unroll
        for (int i = 0; i < 16; i++) {
            wA[i] = __floats2half2_rn(ra[2 * i], ra[2 * i + 1]);
            wB[i] = __floats2half2_rn(rb[2 * i], rb[2 * i + 1]);
        }
    }
    const float wihM  = W_ih[rowAct];
    const float biasM = b_ih[rowAct] + b_hh[rowAct];

    if (tid < Tn) x_sh[tid] = x[b * Tn + tid];
    if (tid < Hn) H16[tid] = __float2half(0.f);   // row 0 = h0 = 0
    __syncthreads();

    // ================= Phase 1: recurrence =================
    float c = 0.f;
#pragma unroll 2
    for (int t = 0; t < Tn; t++) {
        const uint4* hp = (const uint4*)(H16 + t * Hn + k0);
        half2 aA0 = __float2half2_rn(0.f), aA1 = aA0, aB0 = aA0, aB1 = aA0;
#pragma unroll
        for (int q = 0; q < 4; q++) {
            uint4 hv = hp[q];
            half2 h0 = *(const half2*)&hv.x, h1 = *(const half2*)&hv.y;
            half2 h2v = *(const half2*)&hv.z, h3 = *(const half2*)&hv.w;
            aA0 = __hfma2(wA[4 * q + 0], h0, aA0);
            aB0 = __hfma2(wB[4 * q + 0], h0, aB0);
            aA1 = __hfma2(wA[4 * q + 1], h1, aA1);
            aB1 = __hfma2(wB[4 * q + 1], h1, aB1);
            aA0 = __hfma2(wA[4 * q + 2], h2v, aA0);
            aB0 = __hfma2(wB[4 * q + 2], h2v, aB0);
            aA1 = __hfma2(wA[4 * q + 3], h3, aA1);
            aB1 = __hfma2(wB[4 * q + 3], h3, aB1);
        }
        float2 fA = __half22float2(__hadd2(aA0, aA1));
        float2 fB = __half22float2(__hadd2(aB0, aB1));
        float sAx = fA.x + fA.y;
        float sBx = fB.x + fB.y;

        // role-swapped reduction: 2 shuffles reduce BOTH rows.
        float v1 = evenkq ? sBx : sAx;                     // send other row
        float r1 = __shfl_xor_sync(0xffffffffu, v1, 8);
        float s  = (evenkq ? sAx : sBx) + r1;              // pair sum of own role
        s += __shfl_xor_sync(0xffffffffu, s, 16);          // full sum

        float gsum = s + fmaf(x_sh[t], wihM, biasM);
        float act  = fmaf(am, tanh_fast(sc * gsum), ab);   // own gate activation

        float x4v = __shfl_xor_sync(0xffffffffu, act, 4);  // si<->tg, sf<->so
        float itg = act * x4v;                             // valid on even lanes
        float r8  = __shfl_xor_sync(0xffffffffu, itg, 8);  // odd lanes <- itg

        float sfv = p ? x4v : act;                         // odd lanes: sigma(f)
        float sov = p ? act : x4v;                         // odd lanes: sigma(o)
        c = fmaf(sfv, c, r8);                              // valid on odd lanes
        float h = sov * tanh_fast(c);

        if (st_h) H16[(t + 1) * Hn + j] = __float2half_rn(h);
        __syncthreads();
    }

    // ================= Phase 2: a, s, p per t (warp w: rows 8w..8w+7) =======
    for (int i = 0; i < 8; i++) {
        const int t = (w << 3) + i;
        const __half* hrow = H16 + (t + 1) * Hn;
        float h0 = __half2float(hrow[l]);
        float h1 = __half2float(hrow[l + 32]);
        float h2 = __half2float(hrow[l + 64]);
        float h3 = __half2float(hrow[l + 96]);
        float t0 = tanh_fast(h0), t1 = tanh_fast(h1), t2 = tanh_fast(h2), t3 = tanh_fast(h3);

        float v[12];
        v[0] = t0 * w_t[l]       + t1 * w_t[l + 32]  + t2 * w_t[l + 64]  + t3 * w_t[l + 96];
        v[1] = t0 * w_t[128 + l] + t1 * w_t[160 + l] + t2 * w_t[192 + l] + t3 * w_t[224 + l];
#pragma unroll
        for (int cc = 0; cc < Cn; cc++) {
            const float* fw = fc_W + cc * Hn;
            v[2 + cc] = h0 * fw[l] + h1 * fw[l + 32] + h2 * fw[l + 64] + h3 * fw[l + 96];
        }
#pragma unroll
        for (int off = 16; off > 0; off >>= 1)
#pragma unroll
            for (int k = 0; k < 12; k++)
                v[k] += __shfl_xor_sync(0xffffffffu, v[k], off);
        if (l == 0) {
            sA[t] = v[0];
            sS[t] = v[1];
            float* pr = sP + t * 12;
#pragma unroll
            for (int cc = 0; cc < Cn; cc++) pr[cc] = v[2 + cc];
            pr[10] = 0.f; pr[11] = 0.f;
        }
    }
    __syncthreads();

    // ================= Phase 3: attention + output =================
    {
        const int t    = tid >> 2;
        const int part = tid & 3;
        const float at = sA[t];
        float acc[10];
#pragma unroll
        for (int i = 0; i < 10; i++) acc[i] = 0.f;

        const int jmaxW = (w << 3) + 7;            // warp-uniform bound
        for (int jm1 = part; jm1 < jmaxW; jm1 += 4) {
            float wgt = __fdividef(1.f, 1.f + __expf(-(at + sS[jm1])));
            wgt = (jm1 < t) ? wgt : 0.f;
            const float4* q = (const float4*)(sP + jm1 * 12);
            float4 q0 = q[0], q1 = q[1], q2 = q[2];
            acc[0] = fmaf(wgt, q0.x, acc[0]); acc[1] = fmaf(wgt, q0.y, acc[1]);
            acc[2] = fmaf(wgt, q0.z, acc[2]); acc[3] = fmaf(wgt, q0.w, acc[3]);
            acc[4] = fmaf(wgt, q1.x, acc[4]); acc[5] = fmaf(wgt, q1.y, acc[5]);
            acc[6] = fmaf(wgt, q1.z, acc[6]); acc[7] = fmaf(wgt, q1.w, acc[7]);
            acc[8] = fmaf(wgt, q2.x, acc[8]); acc[9] = fmaf(wgt, q2.y, acc[9]);
        }
#pragma unroll
        for (int off = 1; off <= 2; off <<= 1)
#pragma unroll
            for (int i = 0; i < 10; i++)
                acc[i] += __shfl_xor_sync(0xffffffffu, acc[i], off);

        if (part == 0) {
            float* o = out + (b * Tn + t) * Cn;
            const float* pr = sP + t * 12;
#pragma unroll
            for (int i = 0; i < 10; i++)
                o[i] = acc[i] + pr[i] + fc_b[i];
        }
    }
}

// ============================================================================
extern "C" void kernel_launch(void* const* d_in, const int* in_sizes, int n_in,
                              void* d_out, int out_size)
{
    const float* x    = (const float*)d_in[0];
    const float* W_ih = (const float*)d_in[1];
    const float* W_hh = (const float*)d_in[2];
    const float* b_ih = (const float*)d_in[3];
    const float* b_hh = (const float*)d_in[4];
    const float* w_t  = (const float*)d_in[5];
    const float* fc_W = (const float*)d_in[6];
    const float* fc_b = (const float*)d_in[7];
    float* out = (float*)d_out;

    // Idempotent; also runs on the pre-capture correctness call.
    cudaFuncSetAttribute(lstm_fused, cudaFuncAttributeMaxDynamicSharedMemorySize, SMEM_SZ);

    lstm_fused<<<Bn, 1024, SMEM_SZ>>>(x, W_ih, W_hh, b_ih, b_hh,
                                      w_t, fc_W, fc_b, out);
}

// round 14
// speedup vs baseline: 1.5889x; 1.0255x over previous
#include <cuda_runtime.h>
#include <cuda_fp16.h>
#include <cstdint>
#include <math.h>

#define Bn 128
#define Tn 256
#define Hn 128
#define Cn 10

__device__ __forceinline__ float tanh_fast(float v) {
    float y;
    asm("tanh.approx.f32 %0, %1;" : "=f"(y) : "f"(v));
    return y;
}

// smem layout (bytes):
//   0      H16[257][128] fp16 history (row t+1 = h_t; row 0 = h0 = 0)  65792
//   65792  sP[256][12] f32                                            12288
//   78080  sA[256] f32
//   79104  sS[256] f32
//   80128  x_sh[256] f32
#define OFF_SP  65792
#define OFF_SA  78080
#define OFF_SS  79104
#define OFF_X   80128
#define SMEM_SZ 81152

// ---------------------------------------------------------------------------
// Fused kernel, 1024 threads/CTA, CTA b = batch row b.
// Phase 1, R=4 layout: lane l = ke*4 + ju (ke=l>>2 in 0..7, ju=l&3).
//   unit j = 4w + ju; thread computes ALL FOUR gate rows of j over k-eighth
//   [16ke, 16ke+16): 32 HFMA2, 32 weight half2 regs, but only 2 LDS.128 of h
//   (half the L1-wavefront traffic of the R=2 version).
// Role-splitting butterfly over ke bits (q0=ke&1, q1=(ke>>1)&1, q2=ke>>2):
//   xor4: q0=0 keeps (i,g) sends (f,o); q0=1 keeps (f,o) sends (i,g)  [2 shfl]
//   xor8: q1=0 keeps first, q1=1 keeps second                         [1 shfl]
//   xor16: full k sum (q2 duplicates)                                 [1 shfl]
// -> lane owns ONE gate: gsel = q0 + 2*q1 (0:i 1:f 2:g 3:o); 1 MUFU act.
// Dance: x8 = xor8(act) (i<->g, f<->o); itg = act*x8 on q0=0; xor4 ships itg
// to f/o lanes which update c and compute h. Store h from lanes ke==3.
// One __syncthreads per step.
// ---------------------------------------------------------------------------
__global__ __launch_bounds__(1024, 1) void lstm_fused(
    const float* __restrict__ x,
    const float* __restrict__ W_ih,
    const float* __restrict__ W_hh,
    const float* __restrict__ b_ih,
    const float* __restrict__ b_hh,
    const float* __restrict__ w_t,
    const float* __restrict__ fc_W,
    const float* __restrict__ fc_b,
    float* __restrict__ out)
{
    extern __shared__ __align__(16) char smraw[];
    __half* H16  = (__half*)smraw;
    float*  sP   = (float*)(smraw + OFF_SP);
    float*  sA   = (float*)(smraw + OFF_SA);
    float*  sS   = (float*)(smraw + OFF_SS);
    float*  x_sh = (float*)(smraw + OFF_X);

    const int b   = blockIdx.x;
    const int tid = threadIdx.x;
    const int w   = tid >> 5;
    const int l   = tid & 31;
    const int ju  = l & 3;
    const int ke  = l >> 2;              // k-eighth index 0..7
    const int q0  = ke & 1;
    const int q1  = (ke >> 1) & 1;
    const int j   = (w << 2) + ju;       // hidden unit
    const int k0  = ke << 4;             // k-slice start (16 wide)

    const int  gsel   = q0 + 2 * q1;     // 0:i 1:f 2:g 3:o
    const int  rowAct = gsel * Hn + j;
    const bool isg    = (gsel == 2);
    const float sc = isg ? 1.0f : 0.5f;
    const float am = isg ? 1.0f : 0.5f;
    const float ab = isg ? 0.0f : 0.5f;
    const bool st_h = (ke == 3);         // q0=1,q1=1,q2=0 -> one lane per unit

    // ---- weights: 4 gate rows x 8 half2 over the k-eighth ----
    half2 w2[4][8];
#pragma unroll
    for (int r = 0; r < 4; r++) {
        const float* wr = W_hh + (r * Hn + j) * Hn + k0;
#pragma unroll
        for (int i = 0; i < 8; i++)
            w2[r][i] = __floats2half2_rn(wr[2 * i], wr[2 * i + 1]);
    }
    const float wihM  = W_ih[rowAct];
    const float biasM = b_ih[rowAct] + b_hh[rowAct];

    if (tid < Tn) x_sh[tid] = x[b * Tn + tid];
    if (tid < Hn) H16[tid] = __float2half(0.f);   // row 0 = h0 = 0
    __syncthreads();

    // ================= Phase 1: recurrence =================
    float c = 0.f;
#pragma unroll 2
    for (int t = 0; t < Tn; t++) {
        const uint4* hp = (const uint4*)(H16 + t * Hn + k0);
        uint4 hv0 = hp[0], hv1 = hp[1];
        half2 hh[8];
        hh[0] = *(const half2*)&hv0.x; hh[1] = *(const half2*)&hv0.y;
        hh[2] = *(const half2*)&hv0.z; hh[3] = *(const half2*)&hv0.w;
        hh[4] = *(const half2*)&hv1.x; hh[5] = *(const half2*)&hv1.y;
        hh[6] = *(const half2*)&hv1.z; hh[7] = *(const half2*)&hv1.w;

        half2 acc0 = __float2half2_rn(0.f), acc1 = acc0, acc2 = acc0, acc3 = acc0;
#pragma unroll
        for (int i = 0; i < 8; i++) {
            acc0 = __hfma2(w2[0][i], hh[i], acc0);
            acc1 = __hfma2(w2[1][i], hh[i], acc1);
            acc2 = __hfma2(w2[2][i], hh[i], acc2);
            acc3 = __hfma2(w2[3][i], hh[i], acc3);
        }
        float2 f0 = __half22float2(acc0);
        float2 f1 = __half22float2(acc1);
        float2 f2 = __half22float2(acc2);
        float2 f3 = __half22float2(acc3);
        float pi = f0.x + f0.y;   // i-row partial
        float pf = f1.x + f1.y;   // f-row partial
        float pg = f2.x + f2.y;   // g-row partial
        float po = f3.x + f3.y;   // o-row partial

        // round 1 (xor4): q0=0 keeps (i,g) sends (f,o); q0=1 keeps (f,o) sends (i,g)
        float sendA = q0 ? pi : pf;
        float sendB = q0 ? pg : po;
        float keepA = q0 ? pf : pi;
        float keepB = q0 ? po : pg;
        float uA = keepA + __shfl_xor_sync(0xffffffffu, sendA, 4);
        float uB = keepB + __shfl_xor_sync(0xffffffffu, sendB, 4);
        // round 2 (xor8): q1=0 keeps uA, q1=1 keeps uB
        float sendC = q1 ? uA : uB;
        float keepC = q1 ? uB : uA;
        float s = keepC + __shfl_xor_sync(0xffffffffu, sendC, 8);
        // round 3 (xor16): full k sum
        s += __shfl_xor_sync(0xffffffffu, s, 16);

        float gsum = s + fmaf(x_sh[t], wihM, biasM);
        float act  = fmaf(am, tanh_fast(sc * gsum), ab);   // own gate activation

        float x8  = __shfl_xor_sync(0xffffffffu, act, 8);  // i<->g, f<->o
        float tmp = act * x8;                              // q0=0: itg; q0=1: junk
        float x4  = __shfl_xor_sync(0xffffffffu, tmp, 4);  // q0=1 lanes <- itg

        float sfv = q1 ? x8 : act;                         // f/o lanes: sigma(f)
        float sov = q1 ? act : x8;                         // f/o lanes: sigma(o)
        c = fmaf(sfv, c, x4);                              // valid on q0=1 lanes
        float h = sov * tanh_fast(c);

        if (st_h) H16[(t + 1) * Hn + j] = __float2half_rn(h);
        __syncthreads();
    }

    // ================= Phase 2: a, s, p per t (warp w: rows 8w..8w+7) =======
    for (int i = 0; i < 8; i++) {
        const int t = (w << 3) + i;
        const __half* hrow = H16 + (t + 1) * Hn;
        float h0 = __half2float(hrow[l]);
        float h1 = __half2float(hrow[l + 32]);
        float h2 = __half2float(hrow[l + 64]);
        float h3 = __half2float(hrow[l + 96]);
        float t0 = tanh_fast(h0), t1 = tanh_fast(h1), t2 = tanh_fast(h2), t3 = tanh_fast(h3);

        float v[12];
        v[0] = t0 * w_t[l]       + t1 * w_t[l + 32]  + t2 * w_t[l + 64]  + t3 * w_t[l + 96];
        v[1] = t0 * w_t[128 + l] + t1 * w_t[160 + l] + t2 * w_t[192 + l] + t3 * w_t[224 + l];
#pragma unroll
        for (int cc = 0; cc < Cn; cc++) {
            const float* fw = fc_W + cc * Hn;
            v[2 + cc] = h0 * fw[l] + h1 * fw[l + 32] + h2 * fw[l + 64] + h3 * fw[l + 96];
        }
#pragma unroll
        for (int off = 16; off > 0; off >>= 1)
#pragma unroll
            for (int k = 0; k < 12; k++)
                v[k] += __shfl_xor_sync(0xffffffffu, v[k], off);
        if (l == 0) {
            sA[t] = v[0];
            sS[t] = v[1];
            float* pr = sP + t * 12;
#pragma unroll
            for (int cc = 0; cc < Cn; cc++) pr[cc] = v[2 + cc];
            pr[10] = 0.f; pr[11] = 0.f;
        }
    }
    __syncthreads();

    // ================= Phase 3: attention + output =================
    {
        const int t    = tid >> 2;
        const int part = tid & 3;
        const float at = sA[t];
        float acc[10];
#pragma unroll
        for (int i = 0; i < 10; i++) acc[i] = 0.f;

        const int jmaxW = (w << 3) + 7;            // warp-uniform bound
        for (int jm1 = part; jm1 < jmaxW; jm1 += 4) {
            float wgt = __fdividef(1.f, 1.f + __expf(-(at + sS[jm1])));
            wgt = (jm1 < t) ? wgt : 0.f;
            const float4* q = (const float4*)(sP + jm1 * 12);
            float4 q0v = q[0], q1v = q[1], q2v = q[2];
            acc[0] = fmaf(wgt, q0v.x, acc[0]); acc[1] = fmaf(wgt, q0v.y, acc[1]);
            acc[2] = fmaf(wgt, q0v.z, acc[2]); acc[3] = fmaf(wgt, q0v.w, acc[3]);
            acc[4] = fmaf(wgt, q1v.x, acc[4]); acc[5] = fmaf(wgt, q1v.y, acc[5]);
            acc[6] = fmaf(wgt, q1v.z, acc[6]); acc[7] = fmaf(wgt, q1v.w, acc[7]);
            acc[8] = fmaf(wgt, q2v.x, acc[8]); acc[9] = fmaf(wgt, q2v.y, acc[9]);
        }
#pragma unroll
        for (int off = 1; off <= 2; off <<= 1)
#pragma unroll
            for (int i = 0; i < 10; i++)
                acc[i] += __shfl_xor_sync(0xffffffffu, acc[i], off);

        if (part == 0) {
            float* o = out + (b * Tn + t) * Cn;
            const float* pr = sP + t * 12;
#pragma unroll
            for (int i = 0; i < 10; i++)
                o[i] = acc[i] + pr[i] + fc_b[i];
        }
    }
}

// ============================================================================
extern "C" void kernel_launch(void* const* d_in, const int* in_sizes, int n_in,
                              void* d_out, int out_size)
{
    const float* x    = (const float*)d_in[0];
    const float* W_ih = (const float*)d_in[1];
    const float* W_hh = (const float*)d_in[2];
    const float* b_ih = (const float*)d_in[3];
    const float* b_hh = (const float*)d_in[4];
    const float* w_t  = (const float*)d_in[5];
    const float* fc_W = (const float*)d_in[6];
    const float* fc_b = (const float*)d_in[7];
    float* out = (float*)d_out;

    // Idempotent; also runs on the pre-capture correctness call.
    cudaFuncSetAttribute(lstm_fused, cudaFuncAttributeMaxDynamicSharedMemorySize, SMEM_SZ);

    lstm_fused<<<Bn, 1024, SMEM_SZ>>>(x, W_ih, W_hh, b_ih, b_hh,
                                      w_t, fc_W, fc_b, out);
}

// round 17
// speedup vs baseline: 1.7151x; 1.0795x over previous
#include <cuda_runtime.h>
#include <cuda_fp16.h>
#include <cstdint>
#include <math.h>

#define Bn 128
#define Tn 256
#define Hn 128
#define Cn 10

typedef unsigned int u32;

__device__ __forceinline__ float tanh_fast(float v) {
    float y;
    asm("tanh.approx.f32 %0, %1;" : "=f"(y) : "f"(v));
    return y;
}
__device__ __forceinline__ half2 shflx_h2(half2 v, int m) {
    u32 u = *(u32*)&v;
    u = __shfl_xor_sync(0xffffffffu, u, m);
    return *(half2*)&u;
}

// smem layout (bytes):
//   0      H16[257][128] fp16 history (row t+1 = h_t; row 0 = h0 = 0)  65792
//   65792  sP[256][12] f32                                            12288
//   78080  sA[256] f32
//   79104  sS[256] f32
//   80128  x_sh[256] f32
#define OFF_SP  65792
#define OFF_SA  78080
#define OFF_SS  79104
#define OFF_X   80128
#define SMEM_SZ 81152

// ---------------------------------------------------------------------------
// Fused kernel, 1024 threads/CTA, CTA b = batch row b.
// Phase 1, R=4 layout: lane l = ke*4 + ju (ke=l>>2 in 0..7, ju=l&3).
//   unit j = 4w + ju; thread computes ALL FOUR gate rows of j over k-eighth
//   [16ke, 16ke+16): 32 HFMA2, 32 weight half2 regs, 2 LDS.128 of h.
// Packed-fp16 role-splitting butterfly (q0=ke&1, q1=(ke>>1)&1):
//   xor4: q0=0 keeps (i,g) h2-accs, sends (f,o); HADD2 combine   [2 shfl]
//   xor8: q1 selects which of the two survivors to keep          [1 shfl]
//   -> lane owns ONE gate's half2 partial over 64 k; ONE convert to fp32,
//   xor16 completes the k sum                                    [1 shfl]
// gsel = q0 + 2*q1 (0:i 1:f 2:g 3:o); 1 MUFU activation.
// Dance: x8 = xor8(act) (i<->g, f<->o); itg = act*x8 on q0=0; xor4 ships itg
// to f/o lanes which update c and compute h. Store h from lanes ke==3.
// One __syncthreads per step.
// ---------------------------------------------------------------------------
__global__ __launch_bounds__(1024, 1) void lstm_fused(
    const float* __restrict__ x,
    const float* __restrict__ W_ih,
    const float* __restrict__ W_hh,
    const float* __restrict__ b_ih,
    const float* __restrict__ b_hh,
    const float* __restrict__ w_t,
    const float* __restrict__ fc_W,
    const float* __restrict__ fc_b,
    float* __restrict__ out)
{
    extern __shared__ __align__(16) char smraw[];
    __half* H16  = (__half*)smraw;
    float*  sP   = (float*)(smraw + OFF_SP);
    float*  sA   = (float*)(smraw + OFF_SA);
    float*  sS   = (float*)(smraw + OFF_SS);
    float*  x_sh = (float*)(smraw + OFF_X);

    const int b   = blockIdx.x;
    const int tid = threadIdx.x;
    const int w   = tid >> 5;
    const int l   = tid & 31;
    const int ju  = l & 3;
    const int ke  = l >> 2;              // k-eighth index 0..7
    const int q0  = ke & 1;
    const int q1  = (ke >> 1) & 1;
    const int j   = (w << 2) + ju;       // hidden unit
    const int k0  = ke << 4;             // k-slice start (16 wide)

    const int  gsel   = q0 + 2 * q1;     // 0:i 1:f 2:g 3:o
    const int  rowAct = gsel * Hn + j;
    const bool isg    = (gsel == 2);
    const float sc = isg ? 1.0f : 0.5f;
    const float am = isg ? 1.0f : 0.5f;
    const float ab = isg ? 0.0f : 0.5f;
    const bool st_h = (ke == 3);         // one lane per unit

    // ---- weights: 4 gate rows x 8 half2 over the k-eighth ----
    half2 w2[4][8];
#pragma unroll
    for (int r = 0; r < 4; r++) {
        const float* wr = W_hh + (r * Hn + j) * Hn + k0;
#pragma unroll
        for (int i = 0; i < 8; i++)
            w2[r][i] = __floats2half2_rn(wr[2 * i], wr[2 * i + 1]);
    }
    const float wihM  = W_ih[rowAct];
    const float biasM = b_ih[rowAct] + b_hh[rowAct];

    if (tid < Tn) x_sh[tid] = x[b * Tn + tid];
    if (tid < Hn) H16[tid] = __float2half(0.f);   // row 0 = h0 = 0
    __syncthreads();

    // ================= Phase 1: recurrence =================
    float c = 0.f;
#pragma unroll 2
    for (int t = 0; t < Tn; t++) {
        const uint4* hp = (const uint4*)(H16 + t * Hn + k0);
        uint4 hv0 = hp[0], hv1 = hp[1];
        half2 hh[8];
        hh[0] = *(const half2*)&hv0.x; hh[1] = *(const half2*)&hv0.y;
        hh[2] = *(const half2*)&hv0.z; hh[3] = *(const half2*)&hv0.w;
        hh[4] = *(const half2*)&hv1.x; hh[5] = *(const half2*)&hv1.y;
        hh[6] = *(const half2*)&hv1.z; hh[7] = *(const half2*)&hv1.w;

        half2 acc0 = __float2half2_rn(0.f), acc1 = acc0, acc2 = acc0, acc3 = acc0;
#pragma unroll
        for (int i = 0; i < 8; i++) {
            acc0 = __hfma2(w2[0][i], hh[i], acc0);   // i-row
            acc1 = __hfma2(w2[1][i], hh[i], acc1);   // f-row
            acc2 = __hfma2(w2[2][i], hh[i], acc2);   // g-row
            acc3 = __hfma2(w2[3][i], hh[i], acc3);   // o-row
        }

        // round 1 (xor4), packed fp16: q0=0 keeps (i,g) sends (f,o)
        half2 sendA = q0 ? acc0 : acc1;
        half2 sendB = q0 ? acc2 : acc3;
        half2 keepA = q0 ? acc1 : acc0;
        half2 keepB = q0 ? acc3 : acc2;
        half2 uA = __hadd2(keepA, shflx_h2(sendA, 4));
        half2 uB = __hadd2(keepB, shflx_h2(sendB, 4));
        // round 2 (xor8), packed fp16: q1 selects survivor
        half2 sendC = q1 ? uA : uB;
        half2 keepC = q1 ? uB : uA;
        half2 sh2 = __hadd2(keepC, shflx_h2(sendC, 8));
        // single convert, then fp32 k-completion (xor16)
        float2 f2v = __half22float2(sh2);
        float s = f2v.x + f2v.y;
        s += __shfl_xor_sync(0xffffffffu, s, 16);

        float gsum = s + fmaf(x_sh[t], wihM, biasM);
        float act  = fmaf(am, tanh_fast(sc * gsum), ab);   // own gate activation

        float x8  = __shfl_xor_sync(0xffffffffu, act, 8);  // i<->g, f<->o
        float tmp = act * x8;                              // q0=0: itg; q0=1: junk
        float x4  = __shfl_xor_sync(0xffffffffu, tmp, 4);  // q0=1 lanes <- itg

        float sfv = q1 ? x8 : act;                         // f/o lanes: sigma(f)
        float sov = q1 ? act : x8;                         // f/o lanes: sigma(o)
        c = fmaf(sfv, c, x4);                              // valid on q0=1 lanes
        float h = sov * tanh_fast(c);

        if (st_h) H16[(t + 1) * Hn + j] = __float2half_rn(h);
        __syncthreads();
    }

    // ================= Phase 2: a, s, p per t (warp w: rows 8w..8w+7) =======
    for (int i = 0; i < 8; i++) {
        const int t = (w << 3) + i;
        const __half* hrow = H16 + (t + 1) * Hn;
        float h0 = __half2float(hrow[l]);
        float h1 = __half2float(hrow[l + 32]);
        float h2 = __half2float(hrow[l + 64]);
        float h3 = __half2float(hrow[l + 96]);
        float t0 = tanh_fast(h0), t1 = tanh_fast(h1), t2 = tanh_fast(h2), t3 = tanh_fast(h3);

        float v[12];
        v[0] = t0 * w_t[l]       + t1 * w_t[l + 32]  + t2 * w_t[l + 64]  + t3 * w_t[l + 96];
        v[1] = t0 * w_t[128 + l] + t1 * w_t[160 + l] + t2 * w_t[192 + l] + t3 * w_t[224 + l];
#pragma unroll
        for (int cc = 0; cc < Cn; cc++) {
            const float* fw = fc_W + cc * Hn;
            v[2 + cc] = h0 * fw[l] + h1 * fw[l + 32] + h2 * fw[l + 64] + h3 * fw[l + 96];
        }
#pragma unroll
        for (int off = 16; off > 0; off >>= 1)
#pragma unroll
            for (int k = 0; k < 12; k++)
                v[k] += __shfl_xor_sync(0xffffffffu, v[k], off);
        if (l == 0) {
            sA[t] = v[0];
            sS[t] = v[1];
            float* pr = sP + t * 12;
#pragma unroll
            for (int cc = 0; cc < Cn; cc++) pr[cc] = v[2 + cc];
            pr[10] = 0.f; pr[11] = 0.f;
        }
    }
    __syncthreads();

    // ================= Phase 3: attention + output =================
    {
        const int t    = tid >> 2;
        const int part = tid & 3;
        const float at = sA[t];
        float acc[10];
#pragma unroll
        for (int i = 0; i < 10; i++) acc[i] = 0.f;

        const int jmaxW = (w << 3) + 7;            // warp-uniform bound
        for (int jm1 = part; jm1 < jmaxW; jm1 += 4) {
            float wgt = __fdividef(1.f, 1.f + __expf(-(at + sS[jm1])));
            wgt = (jm1 < t) ? wgt : 0.f;
            const float4* q = (const float4*)(sP + jm1 * 12);
            float4 q0v = q[0], q1v = q[1], q2v = q[2];
            acc[0] = fmaf(wgt, q0v.x, acc[0]); acc[1] = fmaf(wgt, q0v.y, acc[1]);
            acc[2] = fmaf(wgt, q0v.z, acc[2]); acc[3] = fmaf(wgt, q0v.w, acc[3]);
            acc[4] = fmaf(wgt, q1v.x, acc[4]); acc[5] = fmaf(wgt, q1v.y, acc[5]);
            acc[6] = fmaf(wgt, q1v.z, acc[6]); acc[7] = fmaf(wgt, q1v.w, acc[7]);
            acc[8] = fmaf(wgt, q2v.x, acc[8]); acc[9] = fmaf(wgt, q2v.y, acc[9]);
        }
#pragma unroll
        for (int off = 1; off <= 2; off <<= 1)
#pragma unroll
            for (int i = 0; i < 10; i++)
                acc[i] += __shfl_xor_sync(0xffffffffu, acc[i], off);

        if (part == 0) {
            float* o = out + (b * Tn + t) * Cn;
            const float* pr = sP + t * 12;
#pragma unroll
            for (int i = 0; i < 10; i++)
                o[i] = acc[i] + pr[i] + fc_b[i];
        }
    }
}

// ============================================================================
extern "C" void kernel_launch(void* const* d_in, const int* in_sizes, int n_in,
                              void* d_out, int out_size)
{
    const float* x    = (const float*)d_in[0];
    const float* W_ih = (const float*)d_in[1];
    const float* W_hh = (const float*)d_in[2];
    const float* b_ih = (const float*)d_in[3];
    const float* b_hh = (const float*)d_in[4];
    const float* w_t  = (const float*)d_in[5];
    const float* fc_W = (const float*)d_in[6];
    const float* fc_b = (const float*)d_in[7];
    float* out = (float*)d_out;

    // Idempotent; also runs on the pre-capture correctness call.
    cudaFuncSetAttribute(lstm_fused, cudaFuncAttributeMaxDynamicSharedMemorySize, SMEM_SZ);

    lstm_fused<<<Bn, 1024, SMEM_SZ>>>(x, W_ih, W_hh, b_ih, b_hh,
                                      w_t, fc_W, fc_b, out);
}